// round 1
// baseline (speedup 1.0000x reference)
#include <cuda_runtime.h>

#define KS      15
#define RAD     7
#define IMGN    8192
#define TW      128
#define TH      64
#define RROWS   (TH + 2*RAD)    /* 78 */
#define RCOLS   (TW + 2*RAD)    /* 142 */
#define RPITCH  144             /* float4-aligned pitch */
#define NWARPS  8
#define THREADS 256

__device__ float g_kx[KS];
__device__ float g_ky[KS];

// Recover separable 1D kernels from the 2D outer-product kernel.
// kernel[i][j] = ky[i]*kx[j], sum(ky)=sum(kx)=1  =>
//   column sums give kx, row sums give ky (exact up to fp rounding).
__global__ void prep_kernel(const float* __restrict__ k2d) {
    int t = threadIdx.x;
    if (t < KS) {
        float sx = 0.f, sy = 0.f;
        #pragma unroll
        for (int i = 0; i < KS; i++) {
            sx += k2d[i * KS + t];   // sum over rows  -> kx[t]
            sy += k2d[t * KS + i];   // sum over cols  -> ky[t]
        }
        g_kx[t] = sx;
        g_ky[t] = sy;
    }
}

__global__ __launch_bounds__(THREADS)
void blur_kernel(const float* __restrict__ in, float* __restrict__ out) {
    __shared__ float s[RROWS][RPITCH];
    __shared__ float skx[KS], sky[KS];

    const int tid  = threadIdx.x;
    const int warp = tid >> 5;
    const int lane = tid & 31;
    const int x0 = blockIdx.x * TW;
    const int y0 = blockIdx.y * TH;

    if (tid < KS)            skx[tid]      = g_kx[tid];
    else if (tid < 2 * KS)   sky[tid - KS] = g_ky[tid - KS];

    // ---- load raw tile (with reflect padding, edge excluded) ----
    for (int r = warp; r < RROWS; r += NWARPS) {
        int gy = y0 - RAD + r;
        gy = (gy < 0) ? -gy : ((gy >= IMGN) ? (2 * IMGN - 2 - gy) : gy);
        const float* rowp = in + (size_t)gy * IMGN;
        for (int c = lane; c < RCOLS; c += 32) {
            int gx = x0 - RAD + c;
            gx = (gx < 0) ? -gx : ((gx >= IMGN) ? (2 * IMGN - 2 - gx) : gx);
            s[r][c] = rowp[gx];
        }
    }
    __syncthreads();

    // ---- horizontal pass, in place (row r owned by warp r%8) ----
    float kx[KS];
    #pragma unroll
    for (int k = 0; k < KS; k++) kx[k] = skx[k];

    const int c0 = 4 * lane;   // this lane's 4 output columns
    for (int r = warp; r < RROWS; r += NWARPS) {
        // window: smem cols c0 .. c0+17, fetched as 5 aligned float4
        float v[20];
        #pragma unroll
        for (int j = 0; j < 5; j++) {
            float4 q = *(const float4*)&s[r][c0 + 4 * j];
            v[4*j+0] = q.x; v[4*j+1] = q.y; v[4*j+2] = q.z; v[4*j+3] = q.w;
        }
        float a0 = 0.f, a1 = 0.f, a2 = 0.f, a3 = 0.f;
        #pragma unroll
        for (int k = 0; k < KS; k++) {
            float w = kx[k];
            a0 = fmaf(w, v[k    ], a0);
            a1 = fmaf(w, v[k + 1], a1);
            a2 = fmaf(w, v[k + 2], a2);
            a3 = fmaf(w, v[k + 3], a3);
        }
        __syncwarp();   // all lanes done reading row r before any overwrite
        *(float4*)&s[r][c0] = make_float4(a0, a1, a2, a3);
        __syncwarp();
    }
    __syncthreads();

    // ---- vertical pass: warp handles out rows 8w..8w+7, lane cols c0..c0+3 ----
    float ky[KS];
    #pragma unroll
    for (int k = 0; k < KS; k++) ky[k] = sky[k];

    float4 acc[8];
    #pragma unroll
    for (int y = 0; y < 8; y++) acc[y] = make_float4(0.f, 0.f, 0.f, 0.f);

    const int rbase = 8 * warp;
    #pragma unroll
    for (int j = 0; j < 22; j++) {       // temp rows rbase+0 .. rbase+21
        float4 t = *(const float4*)&s[rbase + j][c0];
        #pragma unroll
        for (int y = 0; y < 8; y++) {
            int k = j - y;               // compile-time after unroll
            if (k >= 0 && k < KS) {
                float w = ky[k];
                acc[y].x = fmaf(w, t.x, acc[y].x);
                acc[y].y = fmaf(w, t.y, acc[y].y);
                acc[y].z = fmaf(w, t.z, acc[y].z);
                acc[y].w = fmaf(w, t.w, acc[y].w);
            }
        }
    }

    #pragma unroll
    for (int y = 0; y < 8; y++) {
        *(float4*)&out[(size_t)(y0 + rbase + y) * IMGN + x0 + c0] = acc[y];
    }
}

extern "C" void kernel_launch(void* const* d_in, const int* in_sizes, int n_in,
                              void* d_out, int out_size) {
    const float* img = (const float*)d_in[0];
    const float* k2d = (const float*)d_in[1];
    float* out = (float*)d_out;

    prep_kernel<<<1, 32>>>(k2d);
    dim3 grid(IMGN / TW, IMGN / TH);
    blur_kernel<<<grid, THREADS>>>(img, out);
}

// round 14
// speedup vs baseline: 2.1116x; 2.1116x over previous
#include <cuda_runtime.h>

#define KS      15
#define RAD     7
#define IMGN    8192
#define TW      128
#define TH      64
#define RROWS   (TH + 2*RAD)    /* 78 */
#define PITCH   128
#define NWARPS  8
#define THREADS 256

// g_k1d layout: [0..14] = kx, [16..45] = ky duplicated pairs (ky[k],ky[k])
__device__ float g_k1d[48];
__constant__ __align__(16) float c_k[48];

// Recover separable 1D kernels from the 2D outer-product kernel.
// kernel[i][j] = ky[i]*kx[j], sum(ky)=sum(kx)=1  =>
//   column sums give kx, row sums give ky.
__global__ void prep_kernel(const float* __restrict__ k2d) {
    int t = threadIdx.x;
    if (t < KS) {
        float sx = 0.f, sy = 0.f;
        #pragma unroll
        for (int i = 0; i < KS; i++) {
            sx += k2d[i * KS + t];   // sum over rows  -> kx[t]
            sy += k2d[t * KS + i];   // sum over cols  -> ky[t]
        }
        g_k1d[t] = sx;
        g_k1d[16 + 2 * t]     = sy;  // packed pair lo
        g_k1d[16 + 2 * t + 1] = sy;  // packed pair hi
    }
}

__device__ __forceinline__ void ffma2(unsigned long long& d,
                                      unsigned long long a,
                                      unsigned long long b) {
    asm("fma.rn.f32x2 %0, %1, %2, %0;" : "+l"(d) : "l"(a), "l"(b));
}
__device__ __forceinline__ void fmul2(unsigned long long& d,
                                      unsigned long long a,
                                      unsigned long long b) {
    asm("mul.rn.f32x2 %0, %1, %2;" : "=l"(d) : "l"(a), "l"(b));
}

__global__ __launch_bounds__(THREADS, 5)
void blur_kernel(const float* __restrict__ in, float* __restrict__ out) {
    __shared__ float s[RROWS][PITCH];   // H-filtered tile, 39936 B

    const int tid  = threadIdx.x;
    const int warp = tid >> 5;
    const int lane = tid & 31;
    const int bx = blockIdx.x, by = blockIdx.y;
    const int x0 = bx * TW;
    const int y0 = by * TH;
    const int c0 = 4 * lane;
    const bool xsafe = (bx > 0) && (bx < (int)gridDim.x - 1);

    // ---- horizontal pass: global -> registers -> conv -> smem ----
    for (int r = warp; r < RROWS; r += NWARPS) {
        int gy = y0 - RAD + r;
        gy = (gy < 0) ? -gy : ((gy >= IMGN) ? (2 * IMGN - 2 - gy) : gy);
        const float* rowb = in + (size_t)gy * IMGN;

        float v[20];
        if (xsafe) {
            // aligned window [x0+c0-8, x0+c0+12): 5 x LDG.128
            const float4* p = (const float4*)(rowb + x0 + c0 - 8);
            #pragma unroll
            for (int j = 0; j < 5; j++) {
                float4 q = __ldg(p + j);
                v[4*j+0] = q.x; v[4*j+1] = q.y; v[4*j+2] = q.z; v[4*j+3] = q.w;
            }
        } else {
            #pragma unroll
            for (int i = 0; i < 20; i++) {
                int gx = x0 + c0 - 8 + i;
                gx = (gx < 0) ? -gx : ((gx >= IMGN) ? (2 * IMGN - 2 - gx) : gx);
                v[i] = __ldg(rowb + gx);
            }
        }

        float a0 = 0.f, a1 = 0.f, a2 = 0.f, a3 = 0.f;
        #pragma unroll
        for (int k = 0; k < KS; k++) {
            float w = c_k[k];                 // uniform (LDCU -> UR)
            a0 = fmaf(w, v[k + 1], a0);
            a1 = fmaf(w, v[k + 2], a1);
            a2 = fmaf(w, v[k + 3], a2);
            a3 = fmaf(w, v[k + 4], a3);
        }
        *(float4*)&s[r][c0] = make_float4(a0, a1, a2, a3);
    }
    __syncthreads();

    // ---- vertical pass: packed f32x2, 8 output rows per warp ----
    const unsigned long long* kw =
        (const unsigned long long*)(c_k + 16);  // (ky[k],ky[k]) pairs

    unsigned long long accA[8], accB[8];
    const int rbase = 8 * warp;

    #pragma unroll
    for (int j = 0; j < 22; j++) {
        ulonglong2 t = *(const ulonglong2*)&s[rbase + j][c0];
        #pragma unroll
        for (int y = 0; y < 8; y++) {
            int k = j - y;                    // compile-time after unroll
            if (k == 0) {
                fmul2(accA[y], t.x, kw[0]);
                fmul2(accB[y], t.y, kw[0]);
            } else if (k > 0 && k < KS) {
                ffma2(accA[y], t.x, kw[k]);
                ffma2(accB[y], t.y, kw[k]);
            }
        }
    }

    #pragma unroll
    for (int y = 0; y < 8; y++) {
        ulonglong2 r;
        r.x = accA[y];
        r.y = accB[y];
        *(ulonglong2*)(out + (size_t)(y0 + rbase + y) * IMGN + x0 + c0) = r;
    }
}

extern "C" void kernel_launch(void* const* d_in, const int* in_sizes, int n_in,
                              void* d_out, int out_size) {
    const float* img = (const float*)d_in[0];
    const float* k2d = (const float*)d_in[1];
    float* out = (float*)d_out;

    prep_kernel<<<1, 32>>>(k2d);

    void* gptr = nullptr;
    cudaGetSymbolAddress(&gptr, g_k1d);
    cudaMemcpyToSymbolAsync(c_k, gptr, 48 * sizeof(float), 0,
                            cudaMemcpyDeviceToDevice, 0);

    dim3 grid(IMGN / TW, IMGN / TH);
    blur_kernel<<<grid, THREADS>>>(img, out);
}